// round 1
// baseline (speedup 1.0000x reference)
#include <cuda_runtime.h>
#include <cstdint>
#include <cstdio>

// ---------------------------------------------------------------------------
// Problem constants (shapes fixed by the dataset)
// ---------------------------------------------------------------------------
#define NMAX 100000          // N_P == N_A == 100000
#define EMAX 500000
#define H4   4

// ---------------------------------------------------------------------------
// Static device scratch (no allocations allowed)
// ---------------------------------------------------------------------------
__device__ float g_hp[NMAX * 128];     // paper hidden (layer1 F=128, layer2 reuses first 64)
__device__ float g_ha[NMAX * 128];     // author hidden
__device__ float g_zp[NMAX * 128];     // paper layer output
__device__ float g_za[NMAX * 128];     // author layer output
__device__ float g_asrc[NMAX * H4];
__device__ float g_adst[NMAX * H4];
__device__ int   g_offs_pa[NMAX + 1];
__device__ int   g_offs_ap[NMAX + 1];
__device__ int   g_srcs_pa[EMAX];
__device__ int   g_srcs_ap[EMAX];
__device__ int   g_cnt[NMAX];
__device__ int   g_partials[256];

// ---------------------------------------------------------------------------
// CSR build: histogram -> scan -> scatter
// ---------------------------------------------------------------------------
__global__ void hist_kernel(const int* __restrict__ dst, int E, int* __restrict__ cnt) {
    int e = blockIdx.x * blockDim.x + threadIdx.x;
    if (e < E) atomicAdd(&cnt[dst[e]], 1);
}

__global__ void scan_phase1(const int* __restrict__ in, int n,
                            int* __restrict__ offs, int* __restrict__ partials) {
    __shared__ int sh[1024];
    int t = threadIdx.x;
    int i = blockIdx.x * 1024 + t;
    sh[t] = (i < n) ? in[i] : 0;
    __syncthreads();
    #pragma unroll
    for (int off = 1; off < 1024; off <<= 1) {
        int x = (t >= off) ? sh[t - off] : 0;
        __syncthreads();
        sh[t] += x;
        __syncthreads();
    }
    if (i < n) offs[i + 1] = sh[t];
    if (t == 1023) partials[blockIdx.x] = sh[t];
}

__global__ void scan_phase2(int* __restrict__ partials, int nb) {
    __shared__ int sh[256];
    int t = threadIdx.x;
    sh[t] = (t < nb) ? partials[t] : 0;
    __syncthreads();
    #pragma unroll
    for (int off = 1; off < 256; off <<= 1) {
        int x = (t >= off) ? sh[t - off] : 0;
        __syncthreads();
        sh[t] += x;
        __syncthreads();
    }
    if (t < nb) partials[t] = (t == 0) ? 0 : sh[t - 1];  // exclusive
}

__global__ void scan_phase3(int* __restrict__ offs, const int* __restrict__ partials, int n) {
    int i = blockIdx.x * 1024 + threadIdx.x;
    if (i < n) offs[i + 1] += partials[blockIdx.x];
    if (i == 0) offs[0] = 0;
}

__global__ void scatter_kernel(const int* __restrict__ src, const int* __restrict__ dst,
                               int E, int* __restrict__ cursor, int* __restrict__ out_srcs) {
    int e = blockIdx.x * blockDim.x + threadIdx.x;
    if (e >= E) return;
    int d = dst[e];
    int pos = atomicAdd(&cursor[d], 1);
    out_srcs[pos] = src[e];
}

// ---------------------------------------------------------------------------
// GEMM: Y[N,F] = X[N,128] @ W[128,F] + b     (F = 128 or 64)
// 128-row block tile, full W resident in smem, 8xTN register microtile.
// ---------------------------------------------------------------------------
template <int F>
__global__ void __launch_bounds__(256)
gemm_bias_kernel(const float* __restrict__ X, const float* __restrict__ W,
                 const float* __restrict__ bias, float* __restrict__ Y, int N) {
    constexpr int K = 128;
    constexpr int BM = 128;
    constexpr int TN = 8;
    constexpr int NTX = F / TN;       // 16 (F=128) / 8 (F=64)
    constexpr int NTY = 256 / NTX;    // 16 / 32
    constexpr int TM  = BM / NTY;     // 8 / 4
    constexpr int KSTEP = 16;
    constexpr int APITCH = BM + 4;

    extern __shared__ float smem[];
    float* Ws = smem;                     // K*F
    float* As = smem + K * F;             // KSTEP * APITCH

    int tid = threadIdx.x;
    int tx = tid % NTX;
    int ty = tid / NTX;
    int row0 = blockIdx.x * BM;

    // load full W (coalesced float4)
    for (int i = tid * 4; i < K * F; i += 256 * 4)
        *(float4*)&Ws[i] = *(const float4*)&W[i];

    float bv[TN];
    #pragma unroll
    for (int j = 0; j < TN; ++j) bv[j] = bias[tx * TN + j];

    float acc[TM][TN];
    #pragma unroll
    for (int i = 0; i < TM; ++i)
        #pragma unroll
        for (int j = 0; j < TN; ++j) acc[i][j] = 0.f;

    for (int kt = 0; kt < K; kt += KSTEP) {
        __syncthreads();
        // load A chunk transposed: As[k][r]
        for (int i = tid; i < BM * (KSTEP / 4); i += 256) {
            int r = i / (KSTEP / 4);
            int kq = i % (KSTEP / 4);
            int row = row0 + r;
            float4 v = make_float4(0.f, 0.f, 0.f, 0.f);
            if (row < N) v = *(const float4*)&X[(size_t)row * K + kt + kq * 4];
            As[(kq * 4 + 0) * APITCH + r] = v.x;
            As[(kq * 4 + 1) * APITCH + r] = v.y;
            As[(kq * 4 + 2) * APITCH + r] = v.z;
            As[(kq * 4 + 3) * APITCH + r] = v.w;
        }
        __syncthreads();
        #pragma unroll
        for (int kk = 0; kk < KSTEP; ++kk) {
            float a[TM], w[TN];
            #pragma unroll
            for (int i = 0; i < TM; ++i) a[i] = As[kk * APITCH + ty * TM + i];
            #pragma unroll
            for (int j = 0; j < TN; ++j) w[j] = Ws[(kt + kk) * F + tx * TN + j];
            #pragma unroll
            for (int i = 0; i < TM; ++i)
                #pragma unroll
                for (int j = 0; j < TN; ++j)
                    acc[i][j] += a[i] * w[j];
        }
    }

    #pragma unroll
    for (int i = 0; i < TM; ++i) {
        int row = row0 + ty * TM + i;
        if (row < N) {
            #pragma unroll
            for (int j = 0; j < TN; j += 4) {
                float4 o;
                o.x = acc[i][j + 0] + bv[j + 0];
                o.y = acc[i][j + 1] + bv[j + 1];
                o.z = acc[i][j + 2] + bv[j + 2];
                o.w = acc[i][j + 3] + bv[j + 3];
                *(float4*)&Y[(size_t)row * F + tx * TN + j] = o;
            }
        }
    }
}

// ---------------------------------------------------------------------------
// Per-node attention logits: out[n,h] = sum_d H[n, h*D+d] * a[h,d]
// ---------------------------------------------------------------------------
__global__ void node_alpha_kernel(const float* __restrict__ Hf, const float* __restrict__ av,
                                  float* __restrict__ out, int N, int F) {
    int i = blockIdx.x * blockDim.x + threadIdx.x;
    if (i >= N * H4) return;
    int n = i >> 2, h = i & 3;
    int D = F >> 2;
    const float* row = Hf + (size_t)n * F + h * D;
    const float* a = av + h * D;
    float s = 0.f;
    for (int d = 0; d < D; ++d) s += row[d] * a[d];
    out[i] = s;
}

// ---------------------------------------------------------------------------
// Edge-softmax aggregation, warp per dst node, online softmax, atomic-free.
// Out[dst,:] = relu( sum_e softmax_e(leaky(asrc[src]+adst[dst])) * Hsrc[src,:] )
// ---------------------------------------------------------------------------
template <int F>
__global__ void __launch_bounds__(256)
aggregate_kernel(const float* __restrict__ Hsrc, const float* __restrict__ asrc,
                 const float* __restrict__ adst, const int* __restrict__ offs,
                 const int* __restrict__ srcs, float* __restrict__ Out, int Ndst) {
    constexpr int VEC = F / 32;       // 4 (F=128) / 2 (F=64); head = lane/8 for both
    int wid = (blockIdx.x * blockDim.x + threadIdx.x) >> 5;
    int lane = threadIdx.x & 31;
    if (wid >= Ndst) return;
    int beg = offs[wid], end = offs[wid + 1];
    int head = lane >> 3;
    float ad = adst[wid * H4 + head];
    float m = -3.4e38f, l = 0.f;
    float acc[VEC];
    #pragma unroll
    for (int v = 0; v < VEC; ++v) acc[v] = 0.f;

    for (int j = beg; j < end; ++j) {
        int s = srcs[j];
        float a = asrc[s * H4 + head] + ad;
        a = (a >= 0.f) ? a : 0.2f * a;              // leaky_relu
        float mn = fmaxf(m, a);
        float sc = __expf(m - mn);
        float e  = __expf(a - mn);
        l = l * sc + e;
        const float* hp = Hsrc + (size_t)s * F + lane * VEC;
        if (VEC == 4) {
            float4 hv = *(const float4*)hp;
            acc[0] = acc[0] * sc + e * hv.x;
            acc[1] = acc[1] * sc + e * hv.y;
            acc[2] = acc[2] * sc + e * hv.z;
            acc[3] = acc[3] * sc + e * hv.w;
        } else {
            float2 hv = *(const float2*)hp;
            acc[0] = acc[0] * sc + e * hv.x;
            acc[1] = acc[1] * sc + e * hv.y;
        }
        m = mn;
    }
    float inv = 1.f / (l + 1e-16f);
    float* op = Out + (size_t)wid * F + lane * VEC;
    #pragma unroll
    for (int v = 0; v < VEC; ++v) op[v] = fmaxf(acc[v] * inv, 0.f);
}

// ---------------------------------------------------------------------------
// Final link prediction: out[l] = dot(z_p[eli0[l]], z_a[eli1[l]]) over 64 dims
// 16 lanes per edge, each loads a float4.
// ---------------------------------------------------------------------------
__global__ void edge_dot_kernel(const float* __restrict__ zp, const float* __restrict__ za,
                                const int* __restrict__ eli, float* __restrict__ out, int L) {
    int t = blockIdx.x * blockDim.x + threadIdx.x;
    int edge = t >> 4;
    int sub = t & 15;
    if (edge >= L) return;
    int p = eli[edge];
    int a = eli[L + edge];
    float4 u = *(const float4*)(zp + (size_t)p * 64 + sub * 4);
    float4 v = *(const float4*)(za + (size_t)a * 64 + sub * 4);
    float s = u.x * v.x + u.y * v.y + u.z * v.z + u.w * v.w;
    s += __shfl_xor_sync(0xffffffffu, s, 8);
    s += __shfl_xor_sync(0xffffffffu, s, 4);
    s += __shfl_xor_sync(0xffffffffu, s, 2);
    s += __shfl_xor_sync(0xffffffffu, s, 1);
    if (sub == 0) out[edge] = s;
}

// ---------------------------------------------------------------------------
// Host orchestration
// ---------------------------------------------------------------------------
static void build_csr(const int* ei, int E, int Nd, int* offs, int* srcs,
                      int* cnt, int* partials) {
    cudaMemsetAsync(cnt, 0, (size_t)Nd * sizeof(int));
    hist_kernel<<<(E + 255) / 256, 256>>>(ei + E, E, cnt);
    int nb = (Nd + 1023) / 1024;
    scan_phase1<<<nb, 1024>>>(cnt, Nd, offs, partials);
    scan_phase2<<<1, 256>>>(partials, nb);
    scan_phase3<<<nb, 1024>>>(offs, partials, Nd);
    cudaMemcpyAsync(cnt, offs, (size_t)Nd * sizeof(int), cudaMemcpyDeviceToDevice);
    scatter_kernel<<<(E + 255) / 256, 256>>>(ei, ei + E, E, cnt, srcs);
}

template <int F>
static void run_layer(const float* xp, const float* xa,
                      const float* pW, const float* pb,
                      const float* aW, const float* ab,
                      const float* s_pa, const float* d_pa,
                      const float* s_ap, const float* d_ap,
                      float* hp, float* ha, float* zp, float* za,
                      float* asrc, float* adst,
                      const int* offs_pa, const int* srcs_pa,
                      const int* offs_ap, const int* srcs_ap,
                      int NP, int NA) {
    constexpr size_t SMEM = (size_t)(128 * F + 16 * (128 + 4)) * sizeof(float);
    int gb_p = (NP + 127) / 128;
    int gb_a = (NA + 127) / 128;
    gemm_bias_kernel<F><<<gb_p, 256, SMEM>>>(xp, pW, pb, hp, NP);
    gemm_bias_kernel<F><<<gb_a, 256, SMEM>>>(xa, aW, ab, ha, NA);

    int at_p = (NP * H4 + 255) / 256;
    int at_a = (NA * H4 + 255) / 256;
    int ag_a = (NA * 32 + 255) / 256;
    int ag_p = (NP * 32 + 255) / 256;

    // pa edges: src=papers, dst=authors -> out_a
    node_alpha_kernel<<<at_p, 256>>>(hp, s_pa, asrc, NP, F);
    node_alpha_kernel<<<at_a, 256>>>(ha, d_pa, adst, NA, F);
    aggregate_kernel<F><<<ag_a, 256>>>(hp, asrc, adst, offs_pa, srcs_pa, za, NA);

    // ap edges: src=authors, dst=papers -> out_p
    node_alpha_kernel<<<at_a, 256>>>(ha, s_ap, asrc, NA, F);
    node_alpha_kernel<<<at_p, 256>>>(hp, d_ap, adst, NP, F);
    aggregate_kernel<F><<<ag_p, 256>>>(ha, asrc, adst, offs_ap, srcs_ap, zp, NP);
}

extern "C" void kernel_launch(void* const* d_in, const int* in_sizes, int n_in,
                              void* d_out, int out_size) {
    const float* x_paper  = (const float*)d_in[0];
    const float* x_author = (const float*)d_in[1];
    const int*   ei_pa    = (const int*)d_in[2];
    const int*   ei_ap    = (const int*)d_in[3];
    const int*   eli      = (const int*)d_in[4];
    const float* p1W = (const float*)d_in[5];
    const float* p1b = (const float*)d_in[6];
    const float* a1W = (const float*)d_in[7];
    const float* a1b = (const float*)d_in[8];
    const float* s1pa = (const float*)d_in[9];
    const float* d1pa = (const float*)d_in[10];
    const float* s1ap = (const float*)d_in[11];
    const float* d1ap = (const float*)d_in[12];
    // d_in[13..15]: k1W,k1b,q1 -> dead (_group over 1 metapath is identity)
    const float* p2W = (const float*)d_in[16];
    const float* p2b = (const float*)d_in[17];
    const float* a2W = (const float*)d_in[18];
    const float* a2b = (const float*)d_in[19];
    const float* s2pa = (const float*)d_in[20];
    const float* d2pa = (const float*)d_in[21];
    const float* s2ap = (const float*)d_in[22];
    const float* d2ap = (const float*)d_in[23];
    // d_in[24..26]: k2W,k2b,q2 -> dead

    int NP = in_sizes[0] / 128;
    int NA = in_sizes[1] / 128;
    int E  = in_sizes[2] / 2;
    int L  = in_sizes[4] / 2;

    float *hp, *ha, *zp, *za, *asrc, *adst;
    int *offs_pa, *offs_ap, *srcs_pa, *srcs_ap, *cnt, *partials;
    cudaGetSymbolAddress((void**)&hp, g_hp);
    cudaGetSymbolAddress((void**)&ha, g_ha);
    cudaGetSymbolAddress((void**)&zp, g_zp);
    cudaGetSymbolAddress((void**)&za, g_za);
    cudaGetSymbolAddress((void**)&asrc, g_asrc);
    cudaGetSymbolAddress((void**)&adst, g_adst);
    cudaGetSymbolAddress((void**)&offs_pa, g_offs_pa);
    cudaGetSymbolAddress((void**)&offs_ap, g_offs_ap);
    cudaGetSymbolAddress((void**)&srcs_pa, g_srcs_pa);
    cudaGetSymbolAddress((void**)&srcs_ap, g_srcs_ap);
    cudaGetSymbolAddress((void**)&cnt, g_cnt);
    cudaGetSymbolAddress((void**)&partials, g_partials);

    // opt-in smem for the big GEMM tile (idempotent; called every launch)
    cudaFuncSetAttribute(gemm_bias_kernel<128>, cudaFuncAttributeMaxDynamicSharedMemorySize,
                         (int)((128 * 128 + 16 * 132) * sizeof(float)));
    cudaFuncSetAttribute(gemm_bias_kernel<64>, cudaFuncAttributeMaxDynamicSharedMemorySize,
                         (int)((128 * 64 + 16 * 132) * sizeof(float)));

    // CSR (same graph reused by both layers)
    build_csr(ei_pa, E, NA, offs_pa, srcs_pa, cnt, partials);
    build_csr(ei_ap, E, NP, offs_ap, srcs_ap, cnt, partials);

    // Layer 1: F=128, inputs x_*, outputs z in g_zp/g_za
    run_layer<128>(x_paper, x_author, p1W, p1b, a1W, a1b,
                   s1pa, d1pa, s1ap, d1ap,
                   hp, ha, zp, za, asrc, adst,
                   offs_pa, srcs_pa, offs_ap, srcs_ap, NP, NA);

    // Layer 2: F=64, inputs z (128-dim), hidden reuses hp/ha, outputs overwrite zp/za
    run_layer<64>(zp, za, p2W, p2b, a2W, a2b,
                  s2pa, d2pa, s2ap, d2ap,
                  hp, ha, zp, za, asrc, adst,
                  offs_pa, srcs_pa, offs_ap, srcs_ap, NP, NA);

    // Final link prediction
    edge_dot_kernel<<<(L * 16 + 255) / 256, 256>>>(zp, za, eli, (float*)d_out, L);
}

// round 2
// speedup vs baseline: 1.4486x; 1.4486x over previous
#include <cuda_runtime.h>
#include <cstdint>

// ---------------------------------------------------------------------------
// Problem constants
// ---------------------------------------------------------------------------
#define NMAX 100000
#define EMAX 500000
#define H4   4

// ---------------------------------------------------------------------------
// Static device scratch
// ---------------------------------------------------------------------------
__device__ float g_hp[NMAX * 128];
__device__ float g_ha[NMAX * 128];
__device__ float g_zp[NMAX * 128];
__device__ float g_za[NMAX * 128];
__device__ float g_asrc_pa[NMAX * H4];
__device__ float g_adst_pa[NMAX * H4];
__device__ float g_asrc_ap[NMAX * H4];
__device__ float g_adst_ap[NMAX * H4];
__device__ int   g_offs_pa[NMAX + 1];
__device__ int   g_offs_ap[NMAX + 1];
__device__ int   g_srcs_pa[EMAX];
__device__ int   g_srcs_ap[EMAX];
__device__ int   g_cnt[NMAX];
__device__ int   g_cnt2[NMAX];
__device__ int   g_partials[256];
__device__ int   g_partials2[256];

// ---------------------------------------------------------------------------
// CSR build: histogram -> scan -> scatter
// ---------------------------------------------------------------------------
__global__ void hist_kernel(const int* __restrict__ dst, int E, int* __restrict__ cnt) {
    int e = blockIdx.x * blockDim.x + threadIdx.x;
    if (e < E) atomicAdd(&cnt[dst[e]], 1);
}

__global__ void scan_phase1(const int* __restrict__ in, int n,
                            int* __restrict__ offs, int* __restrict__ partials) {
    __shared__ int sh[1024];
    int t = threadIdx.x;
    int i = blockIdx.x * 1024 + t;
    sh[t] = (i < n) ? in[i] : 0;
    __syncthreads();
    #pragma unroll
    for (int off = 1; off < 1024; off <<= 1) {
        int x = (t >= off) ? sh[t - off] : 0;
        __syncthreads();
        sh[t] += x;
        __syncthreads();
    }
    if (i < n) offs[i + 1] = sh[t];
    if (t == 1023) partials[blockIdx.x] = sh[t];
}

__global__ void scan_phase2(int* __restrict__ partials, int nb) {
    __shared__ int sh[256];
    int t = threadIdx.x;
    sh[t] = (t < nb) ? partials[t] : 0;
    __syncthreads();
    #pragma unroll
    for (int off = 1; off < 256; off <<= 1) {
        int x = (t >= off) ? sh[t - off] : 0;
        __syncthreads();
        sh[t] += x;
        __syncthreads();
    }
    if (t < nb) partials[t] = (t == 0) ? 0 : sh[t - 1];  // exclusive
}

__global__ void scan_phase3(int* __restrict__ offs, const int* __restrict__ partials, int n) {
    int i = blockIdx.x * 1024 + threadIdx.x;
    if (i < n) offs[i + 1] += partials[blockIdx.x];
    if (i == 0) offs[0] = 0;
}

__global__ void scatter_kernel(const int* __restrict__ src, const int* __restrict__ dst,
                               int E, int* __restrict__ cursor, int* __restrict__ out_srcs) {
    int e = blockIdx.x * blockDim.x + threadIdx.x;
    if (e >= E) return;
    int d = dst[e];
    int pos = atomicAdd(&cursor[d], 1);
    out_srcs[pos] = src[e];
}

// ---------------------------------------------------------------------------
// tf32 helpers
// ---------------------------------------------------------------------------
__device__ __forceinline__ uint32_t f2tf32(float x) {
    uint32_t r;
    asm("cvt.rna.tf32.f32 %0, %1;" : "=r"(r) : "f"(x));
    return r;
}

__device__ __forceinline__ void mma_tf32(float* c, const uint32_t* a, const uint32_t* b) {
    asm volatile(
        "mma.sync.aligned.m16n8k8.row.col.f32.tf32.tf32.f32 "
        "{%0,%1,%2,%3}, {%4,%5,%6,%7}, {%8,%9}, {%0,%1,%2,%3};\n"
        : "+f"(c[0]), "+f"(c[1]), "+f"(c[2]), "+f"(c[3])
        : "r"(a[0]), "r"(a[1]), "r"(a[2]), "r"(a[3]), "r"(b[0]), "r"(b[1]));
}

// ---------------------------------------------------------------------------
// GEMM: Y[N,BN] = X[N,128] @ W[128,BN] + b   via 3xTF32 split mma.sync.
// BM=128, BK=16, 256 threads (8 warps, 4x2 warp grid; warp tile 32 x BN/2)
// ---------------------------------------------------------------------------
template <int BN>
__global__ void __launch_bounds__(256, 1)
gemm_tf32_kernel(const float* __restrict__ X, const float* __restrict__ W,
                 const float* __restrict__ bias, float* __restrict__ Y, int N) {
    constexpr int K  = 128;
    constexpr int BM = 128;
    constexpr int BK = 16;
    constexpr int AP = BM + 4;      // As pitch
    constexpr int BP = BN + 4;      // Bs pitch
    constexpr int WN = BN / 2;      // warp tile N
    constexpr int FRAG_M = 2;       // 32 rows / 16
    constexpr int FRAG_N = WN / 8;  // 8 (BN=128) or 4 (BN=64)

    __shared__ uint32_t As_hi[BK * AP];
    __shared__ uint32_t As_lo[BK * AP];
    __shared__ uint32_t Bs_hi[BK * BP];
    __shared__ uint32_t Bs_lo[BK * BP];

    int tid  = threadIdx.x;
    int wid  = tid >> 5;
    int lane = tid & 31;
    int warp_m = wid & 3;           // 0..3 -> 32-row slabs
    int warp_n = wid >> 2;          // 0..1 -> WN-col slabs
    int row0 = blockIdx.x * BM;

    float c[FRAG_M][FRAG_N][4];
    #pragma unroll
    for (int i = 0; i < FRAG_M; ++i)
        #pragma unroll
        for (int j = 0; j < FRAG_N; ++j)
            #pragma unroll
            for (int k = 0; k < 4; ++k) c[i][j][k] = 0.f;

    // staging index maps
    int xr = tid >> 1;              // 0..127 row within tile
    int xkb = (tid & 1) * 8;        // k base (0 or 8)
    bool xvalid = (row0 + xr) < N;

    for (int kt = 0; kt < K; kt += BK) {
        __syncthreads();
        // ---- stage X tile (128 x 16) as hi/lo tf32, layout [k][m] ----
        {
            float4 v0 = make_float4(0.f, 0.f, 0.f, 0.f);
            float4 v1 = v0;
            if (xvalid) {
                const float* src = X + (size_t)(row0 + xr) * K + kt + xkb;
                v0 = *(const float4*)(src);
                v1 = *(const float4*)(src + 4);
            }
            float vals[8] = {v0.x, v0.y, v0.z, v0.w, v1.x, v1.y, v1.z, v1.w};
            #pragma unroll
            for (int i = 0; i < 8; ++i) {
                uint32_t hi = f2tf32(vals[i]);
                float lo = vals[i] - __uint_as_float(hi);
                As_hi[(xkb + i) * AP + xr] = hi;
                As_lo[(xkb + i) * AP + xr] = f2tf32(lo);
            }
        }
        // ---- stage W tile (16 x BN), layout [k][n] ----
        {
            constexpr int ITEMS = BK * BN / 256;   // 8 (BN=128) or 4 (BN=64)
            int wk = tid >> 4;                     // 0..15
            int wc = (tid & 15) * ITEMS;
            const float* src = W + (size_t)(kt + wk) * BN + wc;
            #pragma unroll
            for (int q = 0; q < ITEMS; q += 4) {
                float4 v = *(const float4*)(src + q);
                float vv[4] = {v.x, v.y, v.z, v.w};
                #pragma unroll
                for (int i = 0; i < 4; ++i) {
                    uint32_t hi = f2tf32(vv[i]);
                    float lo = vv[i] - __uint_as_float(hi);
                    Bs_hi[wk * BP + wc + q + i] = hi;
                    Bs_lo[wk * BP + wc + q + i] = f2tf32(lo);
                }
            }
        }
        __syncthreads();

        // ---- compute: two k8 sub-steps ----
        #pragma unroll
        for (int kk = 0; kk < BK; kk += 8) {
            uint32_t a_h[FRAG_M][4], a_l[FRAG_M][4];
            int ak = kk + (lane & 3);
            int am = warp_m * 32 + (lane >> 2);
            #pragma unroll
            for (int fm = 0; fm < FRAG_M; ++fm) {
                int m0 = am + fm * 16;
                a_h[fm][0] = As_hi[ak * AP + m0];
                a_h[fm][1] = As_hi[ak * AP + m0 + 8];
                a_h[fm][2] = As_hi[(ak + 4) * AP + m0];
                a_h[fm][3] = As_hi[(ak + 4) * AP + m0 + 8];
                a_l[fm][0] = As_lo[ak * AP + m0];
                a_l[fm][1] = As_lo[ak * AP + m0 + 8];
                a_l[fm][2] = As_lo[(ak + 4) * AP + m0];
                a_l[fm][3] = As_lo[(ak + 4) * AP + m0 + 8];
            }
            uint32_t b_h[FRAG_N][2], b_l[FRAG_N][2];
            int bn0 = warp_n * WN + (lane >> 2);
            #pragma unroll
            for (int fn = 0; fn < FRAG_N; ++fn) {
                int n0 = bn0 + fn * 8;
                b_h[fn][0] = Bs_hi[ak * BP + n0];
                b_h[fn][1] = Bs_hi[(ak + 4) * BP + n0];
                b_l[fn][0] = Bs_lo[ak * BP + n0];
                b_l[fn][1] = Bs_lo[(ak + 4) * BP + n0];
            }
            #pragma unroll
            for (int fm = 0; fm < FRAG_M; ++fm)
                #pragma unroll
                for (int fn = 0; fn < FRAG_N; ++fn) {
                    mma_tf32(c[fm][fn], a_h[fm], b_h[fn]);
                    mma_tf32(c[fm][fn], a_h[fm], b_l[fn]);
                    mma_tf32(c[fm][fn], a_l[fm], b_h[fn]);
                }
        }
    }

    // ---- epilogue: add bias, store ----
    int er = row0 + warp_m * 32 + (lane >> 2);
    int ec0 = warp_n * WN + 2 * (lane & 3);
    #pragma unroll
    for (int fn = 0; fn < FRAG_N; ++fn) {
        int col = ec0 + fn * 8;
        float b0 = bias[col], b1 = bias[col + 1];
        #pragma unroll
        for (int fm = 0; fm < FRAG_M; ++fm) {
            int r = er + fm * 16;
            if (r < N) {
                float2 o = make_float2(c[fm][fn][0] + b0, c[fm][fn][1] + b1);
                *(float2*)&Y[(size_t)r * BN + col] = o;
            }
            if (r + 8 < N) {
                float2 o = make_float2(c[fm][fn][2] + b0, c[fm][fn][3] + b1);
                *(float2*)&Y[(size_t)(r + 8) * BN + col] = o;
            }
        }
    }
}

// ---------------------------------------------------------------------------
// Fused per-node attention logits: one read of H, both src and dst dots.
// ---------------------------------------------------------------------------
template <int F>
__global__ void alpha2_kernel(const float* __restrict__ Hf,
                              const float* __restrict__ avs, const float* __restrict__ avd,
                              float* __restrict__ outs, float* __restrict__ outd, int N) {
    int i = blockIdx.x * blockDim.x + threadIdx.x;
    if (i >= N * H4) return;
    int n = i >> 2, h = i & 3;
    constexpr int D = F / 4;
    const float4* row = (const float4*)(Hf + (size_t)n * F + h * D);
    const float4* as = (const float4*)(avs + h * D);
    const float4* ad = (const float4*)(avd + h * D);
    float ss = 0.f, sd = 0.f;
    #pragma unroll
    for (int d = 0; d < D / 4; ++d) {
        float4 hv = row[d], a = as[d], b = ad[d];
        ss += hv.x * a.x + hv.y * a.y + hv.z * a.z + hv.w * a.w;
        sd += hv.x * b.x + hv.y * b.y + hv.z * b.z + hv.w * b.w;
    }
    outs[i] = ss;
    outd[i] = sd;
}

// ---------------------------------------------------------------------------
// Edge-softmax aggregation, warp per dst node, online softmax, atomic-free.
// ---------------------------------------------------------------------------
template <int F>
__global__ void __launch_bounds__(256)
aggregate_kernel(const float* __restrict__ Hsrc, const float* __restrict__ asrc,
                 const float* __restrict__ adst, const int* __restrict__ offs,
                 const int* __restrict__ srcs, float* __restrict__ Out, int Ndst) {
    constexpr int VEC = F / 32;
    int wid = (blockIdx.x * blockDim.x + threadIdx.x) >> 5;
    int lane = threadIdx.x & 31;
    if (wid >= Ndst) return;
    int beg = offs[wid], end = offs[wid + 1];
    int head = lane >> 3;
    float ad = adst[wid * H4 + head];
    float m = -3.4e38f, l = 0.f;
    float acc[VEC];
    #pragma unroll
    for (int v = 0; v < VEC; ++v) acc[v] = 0.f;

    for (int j = beg; j < end; ++j) {
        int s = srcs[j];
        float a = asrc[s * H4 + head] + ad;
        a = (a >= 0.f) ? a : 0.2f * a;
        float mn = fmaxf(m, a);
        float sc = __expf(m - mn);
        float e  = __expf(a - mn);
        l = l * sc + e;
        const float* hp = Hsrc + (size_t)s * F + lane * VEC;
        if (VEC == 4) {
            float4 hv = *(const float4*)hp;
            acc[0] = acc[0] * sc + e * hv.x;
            acc[1] = acc[1] * sc + e * hv.y;
            acc[2] = acc[2] * sc + e * hv.z;
            acc[3] = acc[3] * sc + e * hv.w;
        } else {
            float2 hv = *(const float2*)hp;
            acc[0] = acc[0] * sc + e * hv.x;
            acc[1] = acc[1] * sc + e * hv.y;
        }
        m = mn;
    }
    float inv = 1.f / (l + 1e-16f);
    float* op = Out + (size_t)wid * F + lane * VEC;
    #pragma unroll
    for (int v = 0; v < VEC; ++v) op[v] = fmaxf(acc[v] * inv, 0.f);
}

// ---------------------------------------------------------------------------
// Final link prediction: out[l] = dot(z_p[eli0[l]], z_a[eli1[l]]) over 64 dims
// ---------------------------------------------------------------------------
__global__ void edge_dot_kernel(const float* __restrict__ zp, const float* __restrict__ za,
                                const int* __restrict__ eli, float* __restrict__ out, int L) {
    int t = blockIdx.x * blockDim.x + threadIdx.x;
    int edge = t >> 4;
    int sub = t & 15;
    if (edge >= L) return;
    int p = eli[edge];
    int a = eli[L + edge];
    float4 u = *(const float4*)(zp + (size_t)p * 64 + sub * 4);
    float4 v = *(const float4*)(za + (size_t)a * 64 + sub * 4);
    float s = u.x * v.x + u.y * v.y + u.z * v.z + u.w * v.w;
    s += __shfl_xor_sync(0xffffffffu, s, 8);
    s += __shfl_xor_sync(0xffffffffu, s, 4);
    s += __shfl_xor_sync(0xffffffffu, s, 2);
    s += __shfl_xor_sync(0xffffffffu, s, 1);
    if (sub == 0) out[edge] = s;
}

// ---------------------------------------------------------------------------
// Host orchestration
// ---------------------------------------------------------------------------
static void build_csr(const int* ei, int E, int Nd, int* offs, int* srcs,
                      int* cnt, int* partials) {
    cudaMemsetAsync(cnt, 0, (size_t)Nd * sizeof(int));
    hist_kernel<<<(E + 255) / 256, 256>>>(ei + E, E, cnt);
    int nb = (Nd + 1023) / 1024;
    scan_phase1<<<nb, 1024>>>(cnt, Nd, offs, partials);
    scan_phase2<<<1, 256>>>(partials, nb);
    scan_phase3<<<nb, 1024>>>(offs, partials, Nd);
    cudaMemcpyAsync(cnt, offs, (size_t)Nd * sizeof(int), cudaMemcpyDeviceToDevice);
    scatter_kernel<<<(E + 255) / 256, 256>>>(ei, ei + E, E, cnt, srcs);
}

extern "C" void kernel_launch(void* const* d_in, const int* in_sizes, int n_in,
                              void* d_out, int out_size) {
    const float* x_paper  = (const float*)d_in[0];
    const float* x_author = (const float*)d_in[1];
    const int*   ei_pa    = (const int*)d_in[2];
    const int*   ei_ap    = (const int*)d_in[3];
    const int*   eli      = (const int*)d_in[4];
    const float* p1W = (const float*)d_in[5];
    const float* p1b = (const float*)d_in[6];
    const float* a1W = (const float*)d_in[7];
    const float* a1b = (const float*)d_in[8];
    const float* s1pa = (const float*)d_in[9];
    const float* d1pa = (const float*)d_in[10];
    const float* s1ap = (const float*)d_in[11];
    const float* d1ap = (const float*)d_in[12];
    // d_in[13..15]: k1W,k1b,q1 dead (_group over one metapath == identity)
    const float* p2W = (const float*)d_in[16];
    const float* p2b = (const float*)d_in[17];
    const float* a2W = (const float*)d_in[18];
    const float* a2b = (const float*)d_in[19];
    const float* s2pa = (const float*)d_in[20];
    const float* d2pa = (const float*)d_in[21];
    const float* s2ap = (const float*)d_in[22];
    const float* d2ap = (const float*)d_in[23];
    // d_in[24..26]: k2W,k2b,q2 dead

    int NP = in_sizes[0] / 128;
    int NA = in_sizes[1] / 128;
    int E  = in_sizes[2] / 2;
    int L  = in_sizes[4] / 2;

    float *hp, *ha, *zp, *za, *asrc_pa, *adst_pa, *asrc_ap, *adst_ap;
    int *offs_pa, *offs_ap, *srcs_pa, *srcs_ap, *cnt, *cnt2, *partials, *partials2;
    cudaGetSymbolAddress((void**)&hp, g_hp);
    cudaGetSymbolAddress((void**)&ha, g_ha);
    cudaGetSymbolAddress((void**)&zp, g_zp);
    cudaGetSymbolAddress((void**)&za, g_za);
    cudaGetSymbolAddress((void**)&asrc_pa, g_asrc_pa);
    cudaGetSymbolAddress((void**)&adst_pa, g_adst_pa);
    cudaGetSymbolAddress((void**)&asrc_ap, g_asrc_ap);
    cudaGetSymbolAddress((void**)&adst_ap, g_adst_ap);
    cudaGetSymbolAddress((void**)&offs_pa, g_offs_pa);
    cudaGetSymbolAddress((void**)&offs_ap, g_offs_ap);
    cudaGetSymbolAddress((void**)&srcs_pa, g_srcs_pa);
    cudaGetSymbolAddress((void**)&srcs_ap, g_srcs_ap);
    cudaGetSymbolAddress((void**)&cnt, g_cnt);
    cudaGetSymbolAddress((void**)&cnt2, g_cnt2);
    cudaGetSymbolAddress((void**)&partials, g_partials);
    cudaGetSymbolAddress((void**)&partials2, g_partials2);

    int gb_p = (NP + 127) / 128;
    int gb_a = (NA + 127) / 128;
    int at_p = (NP * H4 + 255) / 256;
    int at_a = (NA * H4 + 255) / 256;
    int ag_a = (NA * 32 + 255) / 256;
    int ag_p = (NP * 32 + 255) / 256;

    // ---- CSR pa (5 kernels) so that kernel #5 is the tf32 GEMM for ncu ----
    build_csr(ei_pa, E, NA, offs_pa, srcs_pa, cnt, partials);

    // ---- Layer 1 GEMMs (F=128) ----
    gemm_tf32_kernel<128><<<gb_p, 256>>>(x_paper,  p1W, p1b, hp, NP);
    gemm_tf32_kernel<128><<<gb_a, 256>>>(x_author, a1W, a1b, ha, NA);

    // ---- CSR ap ----
    build_csr(ei_ap, E, NP, offs_ap, srcs_ap, cnt2, partials2);

    // ---- Layer 1 attention ----
    alpha2_kernel<128><<<at_p, 256>>>(hp, s1pa, d1ap, asrc_pa, adst_ap, NP);
    alpha2_kernel<128><<<at_a, 256>>>(ha, s1ap, d1pa, asrc_ap, adst_pa, NA);
    aggregate_kernel<128><<<ag_a, 256>>>(hp, asrc_pa, adst_pa, offs_pa, srcs_pa, za, NA);
    aggregate_kernel<128><<<ag_p, 256>>>(ha, asrc_ap, adst_ap, offs_ap, srcs_ap, zp, NP);

    // ---- Layer 2 (K=128 -> F=64) ----
    gemm_tf32_kernel<64><<<gb_p, 256>>>(zp, p2W, p2b, hp, NP);
    gemm_tf32_kernel<64><<<gb_a, 256>>>(za, a2W, a2b, ha, NA);
    alpha2_kernel<64><<<at_p, 256>>>(hp, s2pa, d2ap, asrc_pa, adst_ap, NP);
    alpha2_kernel<64><<<at_a, 256>>>(ha, s2ap, d2pa, asrc_ap, adst_pa, NA);
    aggregate_kernel<64><<<ag_a, 256>>>(hp, asrc_pa, adst_pa, offs_pa, srcs_pa, za, NA);
    aggregate_kernel<64><<<ag_p, 256>>>(ha, asrc_ap, adst_ap, offs_ap, srcs_ap, zp, NP);

    // ---- Link prediction ----
    edge_dot_kernel<<<(L * 16 + 255) / 256, 256>>>(zp, za, eli, (float*)d_out, L);
}

// round 3
// speedup vs baseline: 1.7683x; 1.2208x over previous
#include <cuda_runtime.h>
#include <cuda_fp16.h>
#include <cstdint>

// ---------------------------------------------------------------------------
// Problem constants
// ---------------------------------------------------------------------------
#define NMAX 100000
#define EMAX 500000
#define H4   4

// ---------------------------------------------------------------------------
// Static device scratch
// ---------------------------------------------------------------------------
__device__ float g_hp[NMAX * 128];
__device__ float g_ha[NMAX * 128];
__device__ float g_zp[NMAX * 128];
__device__ float g_za[NMAX * 128];
__device__ float g_asrc_pa[NMAX * H4];
__device__ float g_adst_pa[NMAX * H4];
__device__ float g_asrc_ap[NMAX * H4];
__device__ float g_adst_ap[NMAX * H4];
__device__ int   g_offs_pa[NMAX + 1];
__device__ int   g_offs_ap[NMAX + 1];
__device__ int   g_srcs_pa[EMAX];
__device__ int   g_srcs_ap[EMAX];
__device__ int   g_cnt[NMAX];
__device__ int   g_cnt2[NMAX];
__device__ int   g_partials[256];
__device__ int   g_partials2[256];

// ---------------------------------------------------------------------------
// CSR build: histogram -> scan -> scatter
// ---------------------------------------------------------------------------
__global__ void hist_kernel(const int* __restrict__ dst, int E, int* __restrict__ cnt) {
    int e = blockIdx.x * blockDim.x + threadIdx.x;
    if (e < E) atomicAdd(&cnt[dst[e]], 1);
}

__global__ void scan_phase1(const int* __restrict__ in, int n,
                            int* __restrict__ offs, int* __restrict__ partials) {
    __shared__ int sh[1024];
    int t = threadIdx.x;
    int i = blockIdx.x * 1024 + t;
    sh[t] = (i < n) ? in[i] : 0;
    __syncthreads();
    #pragma unroll
    for (int off = 1; off < 1024; off <<= 1) {
        int x = (t >= off) ? sh[t - off] : 0;
        __syncthreads();
        sh[t] += x;
        __syncthreads();
    }
    if (i < n) offs[i + 1] = sh[t];
    if (t == 1023) partials[blockIdx.x] = sh[t];
}

__global__ void scan_phase2(int* __restrict__ partials, int nb) {
    __shared__ int sh[256];
    int t = threadIdx.x;
    sh[t] = (t < nb) ? partials[t] : 0;
    __syncthreads();
    #pragma unroll
    for (int off = 1; off < 256; off <<= 1) {
        int x = (t >= off) ? sh[t - off] : 0;
        __syncthreads();
        sh[t] += x;
        __syncthreads();
    }
    if (t < nb) partials[t] = (t == 0) ? 0 : sh[t - 1];  // exclusive
}

__global__ void scan_phase3(int* __restrict__ offs, const int* __restrict__ partials, int n) {
    int i = blockIdx.x * 1024 + threadIdx.x;
    if (i < n) offs[i + 1] += partials[blockIdx.x];
    if (i == 0) offs[0] = 0;
}

__global__ void scatter_kernel(const int* __restrict__ src, const int* __restrict__ dst,
                               int E, int* __restrict__ cursor, int* __restrict__ out_srcs) {
    int e = blockIdx.x * blockDim.x + threadIdx.x;
    if (e >= E) return;
    int d = dst[e];
    int pos = atomicAdd(&cursor[d], 1);
    out_srcs[pos] = src[e];
}

// ---------------------------------------------------------------------------
// fp16 MMA helper: m16n8k16 row.col, fp32 accumulate
// ---------------------------------------------------------------------------
__device__ __forceinline__ void mma_f16(float* c, const uint32_t* a, const uint32_t* b) {
    asm volatile(
        "mma.sync.aligned.m16n8k16.row.col.f32.f16.f16.f32 "
        "{%0,%1,%2,%3}, {%4,%5,%6,%7}, {%8,%9}, {%0,%1,%2,%3};\n"
        : "+f"(c[0]), "+f"(c[1]), "+f"(c[2]), "+f"(c[3])
        : "r"(a[0]), "r"(a[1]), "r"(a[2]), "r"(a[3]), "r"(b[0]), "r"(b[1]));
}

// ---------------------------------------------------------------------------
// GEMM: Y[N,BN] = X[N,128] @ W[128,BN] + b  via fp16-split 3-pass mma.sync.
// x = hi + lo (each fp16, ~22 effective mantissa bits); y = hh + hl + lh.
// BM=128, BK=16, 256 threads, 8 warps (4x2), warp tile 32 x BN/2.
// ---------------------------------------------------------------------------
template <int BN>
__global__ void __launch_bounds__(256, 1)
gemm_f16_kernel(const float* __restrict__ X, const float* __restrict__ W,
                const float* __restrict__ bias, float* __restrict__ Y, int N) {
    constexpr int K  = 128;
    constexpr int BM = 128;
    constexpr int BK = 16;
    constexpr int AP = BK + 2;      // A pitch in halves (per row of 16 halves)
    constexpr int BP = BK + 2;      // B pitch in halves
    constexpr int WN = BN / 2;
    constexpr int FRAG_M = 2;
    constexpr int FRAG_N = WN / 8;  // 8 (BN=128) / 4 (BN=64)

    __shared__ __half As_hi[BM * AP];   // [m][k]
    __shared__ __half As_lo[BM * AP];
    __shared__ __half Bs_hi[BN * BP];   // [n][k]
    __shared__ __half Bs_lo[BN * BP];

    int tid  = threadIdx.x;
    int wid  = tid >> 5;
    int lane = tid & 31;
    int warp_m = wid & 3;
    int warp_n = wid >> 2;
    int row0 = blockIdx.x * BM;

    float c[FRAG_M][FRAG_N][4];
    #pragma unroll
    for (int i = 0; i < FRAG_M; ++i)
        #pragma unroll
        for (int j = 0; j < FRAG_N; ++j)
            #pragma unroll
            for (int k = 0; k < 4; ++k) c[i][j][k] = 0.f;

    int xr  = tid >> 1;
    int xkb = (tid & 1) * 8;
    bool xvalid = (row0 + xr) < N;

    int lq = lane >> 2;        // 0..7
    int lr = (lane & 3) * 2;   // 0,2,4,6

    for (int kt = 0; kt < K; kt += BK) {
        __syncthreads();
        // ---- stage X tile (128 x 16) as hi/lo fp16, layout [m][k] ----
        {
            float4 v0 = make_float4(0.f, 0.f, 0.f, 0.f);
            float4 v1 = v0;
            if (xvalid) {
                const float* src = X + (size_t)(row0 + xr) * K + kt + xkb;
                v0 = *(const float4*)(src);
                v1 = *(const float4*)(src + 4);
            }
            float vals[8] = {v0.x, v0.y, v0.z, v0.w, v1.x, v1.y, v1.z, v1.w};
            #pragma unroll
            for (int i = 0; i < 8; ++i) {
                __half hi = __float2half_rn(vals[i]);
                float lo = vals[i] - __half2float(hi);
                As_hi[xr * AP + xkb + i] = hi;
                As_lo[xr * AP + xkb + i] = __float2half_rn(lo);
            }
        }
        // ---- stage W tile (16 x BN) transposed to [n][k] ----
        {
            constexpr int ITEMS = BK * BN / 256;   // 8 (BN=128) / 4 (BN=64)
            int wk = tid >> 4;                     // 0..15
            int wc = (tid & 15) * ITEMS;
            const float* src = W + (size_t)(kt + wk) * BN + wc;
            #pragma unroll
            for (int q = 0; q < ITEMS; q += 4) {
                float4 v = *(const float4*)(src + q);
                float vv[4] = {v.x, v.y, v.z, v.w};
                #pragma unroll
                for (int i = 0; i < 4; ++i) {
                    __half hi = __float2half_rn(vv[i]);
                    float lo = vv[i] - __half2float(hi);
                    Bs_hi[(wc + q + i) * BP + wk] = hi;
                    Bs_lo[(wc + q + i) * BP + wk] = __float2half_rn(lo);
                }
            }
        }
        __syncthreads();

        // ---- fragments ----
        uint32_t a_hi[FRAG_M][4], a_lo[FRAG_M][4];
        #pragma unroll
        for (int fm = 0; fm < FRAG_M; ++fm) {
            int r0 = warp_m * 32 + fm * 16 + lq;
            a_hi[fm][0] = *(const uint32_t*)&As_hi[(r0    ) * AP + lr];
            a_hi[fm][1] = *(const uint32_t*)&As_hi[(r0 + 8) * AP + lr];
            a_hi[fm][2] = *(const uint32_t*)&As_hi[(r0    ) * AP + lr + 8];
            a_hi[fm][3] = *(const uint32_t*)&As_hi[(r0 + 8) * AP + lr + 8];
            a_lo[fm][0] = *(const uint32_t*)&As_lo[(r0    ) * AP + lr];
            a_lo[fm][1] = *(const uint32_t*)&As_lo[(r0 + 8) * AP + lr];
            a_lo[fm][2] = *(const uint32_t*)&As_lo[(r0    ) * AP + lr + 8];
            a_lo[fm][3] = *(const uint32_t*)&As_lo[(r0 + 8) * AP + lr + 8];
        }
        uint32_t b_hi[FRAG_N][2], b_lo[FRAG_N][2];
        #pragma unroll
        for (int fn = 0; fn < FRAG_N; ++fn) {
            int n0 = warp_n * WN + fn * 8 + lq;
            b_hi[fn][0] = *(const uint32_t*)&Bs_hi[n0 * BP + lr];
            b_hi[fn][1] = *(const uint32_t*)&Bs_hi[n0 * BP + lr + 8];
            b_lo[fn][0] = *(const uint32_t*)&Bs_lo[n0 * BP + lr];
            b_lo[fn][1] = *(const uint32_t*)&Bs_lo[n0 * BP + lr + 8];
        }
        #pragma unroll
        for (int fm = 0; fm < FRAG_M; ++fm)
            #pragma unroll
            for (int fn = 0; fn < FRAG_N; ++fn) {
                mma_f16(c[fm][fn], a_hi[fm], b_hi[fn]);
                mma_f16(c[fm][fn], a_hi[fm], b_lo[fn]);
                mma_f16(c[fm][fn], a_lo[fm], b_hi[fn]);
            }
    }

    // ---- epilogue: add bias, store ----
    int er = row0 + warp_m * 32 + lq;
    int ec0 = warp_n * WN + lr;
    #pragma unroll
    for (int fn = 0; fn < FRAG_N; ++fn) {
        int col = ec0 + fn * 8;
        float b0 = bias[col], b1 = bias[col + 1];
        #pragma unroll
        for (int fm = 0; fm < FRAG_M; ++fm) {
            int r = er + fm * 16;
            if (r < N) {
                float2 o = make_float2(c[fm][fn][0] + b0, c[fm][fn][1] + b1);
                *(float2*)&Y[(size_t)r * BN + col] = o;
            }
            if (r + 8 < N) {
                float2 o = make_float2(c[fm][fn][2] + b0, c[fm][fn][3] + b1);
                *(float2*)&Y[(size_t)(r + 8) * BN + col] = o;
            }
        }
    }
}

// ---------------------------------------------------------------------------
// Fused per-node attention logits: one read of H, both src and dst dots.
// ---------------------------------------------------------------------------
template <int F>
__global__ void alpha2_kernel(const float* __restrict__ Hf,
                              const float* __restrict__ avs, const float* __restrict__ avd,
                              float* __restrict__ outs, float* __restrict__ outd, int N) {
    int i = blockIdx.x * blockDim.x + threadIdx.x;
    if (i >= N * H4) return;
    int n = i >> 2, h = i & 3;
    constexpr int D = F / 4;
    const float4* row = (const float4*)(Hf + (size_t)n * F + h * D);
    const float4* as = (const float4*)(avs + h * D);
    const float4* ad = (const float4*)(avd + h * D);
    float ss = 0.f, sd = 0.f;
    #pragma unroll
    for (int d = 0; d < D / 4; ++d) {
        float4 hv = row[d], a = as[d], b = ad[d];
        ss += hv.x * a.x + hv.y * a.y + hv.z * a.z + hv.w * a.w;
        sd += hv.x * b.x + hv.y * b.y + hv.z * b.z + hv.w * b.w;
    }
    outs[i] = ss;
    outd[i] = sd;
}

// ---------------------------------------------------------------------------
// Edge-softmax aggregation, warp per dst node, online softmax, atomic-free.
// Next-index prefetch raises loop MLP from 1 to ~2.
// ---------------------------------------------------------------------------
template <int F>
__global__ void __launch_bounds__(256)
aggregate_kernel(const float* __restrict__ Hsrc, const float* __restrict__ asrc,
                 const float* __restrict__ adst, const int* __restrict__ offs,
                 const int* __restrict__ srcs, float* __restrict__ Out, int Ndst) {
    constexpr int VEC = F / 32;
    int wid = (blockIdx.x * blockDim.x + threadIdx.x) >> 5;
    int lane = threadIdx.x & 31;
    if (wid >= Ndst) return;
    int beg = offs[wid], end = offs[wid + 1];
    int head = lane >> 3;
    float ad = adst[wid * H4 + head];
    float m = -3.4e38f, l = 0.f;
    float acc[VEC];
    #pragma unroll
    for (int v = 0; v < VEC; ++v) acc[v] = 0.f;

    int s_next = (beg < end) ? srcs[beg] : 0;
    for (int j = beg; j < end; ++j) {
        int s = s_next;
        if (j + 1 < end) s_next = srcs[j + 1];
        float a = asrc[s * H4 + head] + ad;
        a = (a >= 0.f) ? a : 0.2f * a;
        float mn = fmaxf(m, a);
        float sc = __expf(m - mn);
        float e  = __expf(a - mn);
        l = l * sc + e;
        const float* hp = Hsrc + (size_t)s * F + lane * VEC;
        if (VEC == 4) {
            float4 hv = *(const float4*)hp;
            acc[0] = acc[0] * sc + e * hv.x;
            acc[1] = acc[1] * sc + e * hv.y;
            acc[2] = acc[2] * sc + e * hv.z;
            acc[3] = acc[3] * sc + e * hv.w;
        } else {
            float2 hv = *(const float2*)hp;
            acc[0] = acc[0] * sc + e * hv.x;
            acc[1] = acc[1] * sc + e * hv.y;
        }
        m = mn;
    }
    float inv = 1.f / (l + 1e-16f);
    float* op = Out + (size_t)wid * F + lane * VEC;
    #pragma unroll
    for (int v = 0; v < VEC; ++v) op[v] = fmaxf(acc[v] * inv, 0.f);
}

// ---------------------------------------------------------------------------
// Final link prediction: out[l] = dot(z_p[eli0[l]], z_a[eli1[l]]) over 64 dims
// ---------------------------------------------------------------------------
__global__ void edge_dot_kernel(const float* __restrict__ zp, const float* __restrict__ za,
                                const int* __restrict__ eli, float* __restrict__ out, int L) {
    int t = blockIdx.x * blockDim.x + threadIdx.x;
    int edge = t >> 4;
    int sub = t & 15;
    if (edge >= L) return;
    int p = eli[edge];
    int a = eli[L + edge];
    float4 u = *(const float4*)(zp + (size_t)p * 64 + sub * 4);
    float4 v = *(const float4*)(za + (size_t)a * 64 + sub * 4);
    float s = u.x * v.x + u.y * v.y + u.z * v.z + u.w * v.w;
    s += __shfl_xor_sync(0xffffffffu, s, 8);
    s += __shfl_xor_sync(0xffffffffu, s, 4);
    s += __shfl_xor_sync(0xffffffffu, s, 2);
    s += __shfl_xor_sync(0xffffffffu, s, 1);
    if (sub == 0) out[edge] = s;
}

// ---------------------------------------------------------------------------
// Host orchestration
// ---------------------------------------------------------------------------
static void build_csr(const int* ei, int E, int Nd, int* offs, int* srcs,
                      int* cnt, int* partials) {
    cudaMemsetAsync(cnt, 0, (size_t)Nd * sizeof(int));
    hist_kernel<<<(E + 255) / 256, 256>>>(ei + E, E, cnt);
    int nb = (Nd + 1023) / 1024;
    scan_phase1<<<nb, 1024>>>(cnt, Nd, offs, partials);
    scan_phase2<<<1, 256>>>(partials, nb);
    scan_phase3<<<nb, 1024>>>(offs, partials, Nd);
    cudaMemcpyAsync(cnt, offs, (size_t)Nd * sizeof(int), cudaMemcpyDeviceToDevice);
    scatter_kernel<<<(E + 255) / 256, 256>>>(ei, ei + E, E, cnt, srcs);
}

extern "C" void kernel_launch(void* const* d_in, const int* in_sizes, int n_in,
                              void* d_out, int out_size) {
    const float* x_paper  = (const float*)d_in[0];
    const float* x_author = (const float*)d_in[1];
    const int*   ei_pa    = (const int*)d_in[2];
    const int*   ei_ap    = (const int*)d_in[3];
    const int*   eli      = (const int*)d_in[4];
    const float* p1W = (const float*)d_in[5];
    const float* p1b = (const float*)d_in[6];
    const float* a1W = (const float*)d_in[7];
    const float* a1b = (const float*)d_in[8];
    const float* s1pa = (const float*)d_in[9];
    const float* d1pa = (const float*)d_in[10];
    const float* s1ap = (const float*)d_in[11];
    const float* d1ap = (const float*)d_in[12];
    // d_in[13..15]: k1W,k1b,q1 dead (_group over one metapath == identity)
    const float* p2W = (const float*)d_in[16];
    const float* p2b = (const float*)d_in[17];
    const float* a2W = (const float*)d_in[18];
    const float* a2b = (const float*)d_in[19];
    const float* s2pa = (const float*)d_in[20];
    const float* d2pa = (const float*)d_in[21];
    const float* s2ap = (const float*)d_in[22];
    const float* d2ap = (const float*)d_in[23];
    // d_in[24..26]: k2W,k2b,q2 dead

    int NP = in_sizes[0] / 128;
    int NA = in_sizes[1] / 128;
    int E  = in_sizes[2] / 2;
    int L  = in_sizes[4] / 2;

    float *hp, *ha, *zp, *za, *asrc_pa, *adst_pa, *asrc_ap, *adst_ap;
    int *offs_pa, *offs_ap, *srcs_pa, *srcs_ap, *cnt, *cnt2, *partials, *partials2;
    cudaGetSymbolAddress((void**)&hp, g_hp);
    cudaGetSymbolAddress((void**)&ha, g_ha);
    cudaGetSymbolAddress((void**)&zp, g_zp);
    cudaGetSymbolAddress((void**)&za, g_za);
    cudaGetSymbolAddress((void**)&asrc_pa, g_asrc_pa);
    cudaGetSymbolAddress((void**)&adst_pa, g_adst_pa);
    cudaGetSymbolAddress((void**)&asrc_ap, g_asrc_ap);
    cudaGetSymbolAddress((void**)&adst_ap, g_adst_ap);
    cudaGetSymbolAddress((void**)&offs_pa, g_offs_pa);
    cudaGetSymbolAddress((void**)&offs_ap, g_offs_ap);
    cudaGetSymbolAddress((void**)&srcs_pa, g_srcs_pa);
    cudaGetSymbolAddress((void**)&srcs_ap, g_srcs_ap);
    cudaGetSymbolAddress((void**)&cnt, g_cnt);
    cudaGetSymbolAddress((void**)&cnt2, g_cnt2);
    cudaGetSymbolAddress((void**)&partials, g_partials);
    cudaGetSymbolAddress((void**)&partials2, g_partials2);

    int gb_p = (NP + 127) / 128;
    int gb_a = (NA + 127) / 128;
    int at_p = (NP * H4 + 255) / 256;
    int at_a = (NA * H4 + 255) / 256;
    int ag_a = (NA * 32 + 255) / 256;
    int ag_p = (NP * 32 + 255) / 256;
    int nb   = (NMAX + 1023) / 1024;

    // ---- CSR-pa interleaved with first GEMM: launch #5 (ncu capture slot)
    //      is the F=128 fp16-split GEMM.  GEMM has no dependency on CSR.
    cudaMemsetAsync(cnt, 0, (size_t)NA * sizeof(int));                       // 1
    hist_kernel<<<(E + 255) / 256, 256>>>(ei_pa + E, E, cnt);                // 2
    scan_phase1<<<nb, 1024>>>(cnt, NA, offs_pa, partials);                   // 3
    scan_phase2<<<1, 256>>>(partials, nb);                                   // 4
    gemm_f16_kernel<128><<<gb_p, 256>>>(x_paper, p1W, p1b, hp, NP);          // 5 <- ncu
    scan_phase3<<<nb, 1024>>>(offs_pa, partials, NA);                        // 6
    cudaMemcpyAsync(cnt, offs_pa, (size_t)NA * sizeof(int), cudaMemcpyDeviceToDevice);
    scatter_kernel<<<(E + 255) / 256, 256>>>(ei_pa, ei_pa + E, E, cnt, srcs_pa);
    gemm_f16_kernel<128><<<gb_a, 256>>>(x_author, a1W, a1b, ha, NA);

    // ---- CSR ap ----
    build_csr(ei_ap, E, NP, offs_ap, srcs_ap, cnt2, partials2);

    // ---- Layer 1 attention ----
    alpha2_kernel<128><<<at_p, 256>>>(hp, s1pa, d1ap, asrc_pa, adst_ap, NP);
    alpha2_kernel<128><<<at_a, 256>>>(ha, s1ap, d1pa, asrc_ap, adst_pa, NA);
    aggregate_kernel<128><<<ag_a, 256>>>(hp, asrc_pa, adst_pa, offs_pa, srcs_pa, za, NA);
    aggregate_kernel<128><<<ag_p, 256>>>(ha, asrc_ap, adst_ap, offs_ap, srcs_ap, zp, NP);

    // ---- Layer 2 (K=128 -> F=64) ----
    gemm_f16_kernel<64><<<gb_p, 256>>>(zp, p2W, p2b, hp, NP);
    gemm_f16_kernel<64><<<gb_a, 256>>>(za, a2W, a2b, ha, NA);
    alpha2_kernel<64><<<at_p, 256>>>(hp, s2pa, d2ap, asrc_pa, adst_ap, NP);
    alpha2_kernel<64><<<at_a, 256>>>(ha, s2ap, d2pa, asrc_ap, adst_pa, NA);
    aggregate_kernel<64><<<ag_a, 256>>>(hp, asrc_pa, adst_pa, offs_pa, srcs_pa, za, NA);
    aggregate_kernel<64><<<ag_p, 256>>>(ha, asrc_ap, adst_ap, offs_ap, srcs_ap, zp, NP);

    // ---- Link prediction ----
    edge_dot_kernel<<<(L * 16 + 255) / 256, 256>>>(zp, za, eli, (float*)d_out, L);
}

// round 4
// speedup vs baseline: 1.9906x; 1.1257x over previous
#include <cuda_runtime.h>
#include <cuda_fp16.h>
#include <cstdint>

// ---------------------------------------------------------------------------
// Problem constants
// ---------------------------------------------------------------------------
#define NMAX 100000
#define EMAX 500000
#define H4   4

// ---------------------------------------------------------------------------
// Static device scratch
// ---------------------------------------------------------------------------
__device__ float g_hp[NMAX * 128];
__device__ float g_ha[NMAX * 128];
__device__ float g_zp[NMAX * 128];
__device__ float g_za[NMAX * 128];
__device__ float g_asrc_pa[NMAX * H4];
__device__ float g_adst_pa[NMAX * H4];
__device__ float g_asrc_ap[NMAX * H4];
__device__ float g_adst_ap[NMAX * H4];
__device__ int   g_offs_pa[NMAX + 1];
__device__ int   g_offs_ap[NMAX + 1];
__device__ int   g_srcs_pa[EMAX];
__device__ int   g_srcs_ap[EMAX];
__device__ int   g_cnt[NMAX];
__device__ int   g_cnt2[NMAX];
__device__ int   g_partials[256];
__device__ int   g_partials2[256];
// pre-split weights: [n][K] layout, hi/lo fp16.  4 slots: p1,a1,p2,a2
__device__ __half g_wh[4][128 * 128];
__device__ __half g_wl[4][128 * 128];

// ---------------------------------------------------------------------------
// CSR build: histogram -> scan -> scatter
// ---------------------------------------------------------------------------
__global__ void hist_kernel(const int* __restrict__ dst, int E, int* __restrict__ cnt) {
    int e = blockIdx.x * blockDim.x + threadIdx.x;
    if (e < E) atomicAdd(&cnt[dst[e]], 1);
}

__global__ void scan_phase1(const int* __restrict__ in, int n,
                            int* __restrict__ offs, int* __restrict__ partials) {
    __shared__ int sh[1024];
    int t = threadIdx.x;
    int i = blockIdx.x * 1024 + t;
    sh[t] = (i < n) ? in[i] : 0;
    __syncthreads();
    #pragma unroll
    for (int off = 1; off < 1024; off <<= 1) {
        int x = (t >= off) ? sh[t - off] : 0;
        __syncthreads();
        sh[t] += x;
        __syncthreads();
    }
    if (i < n) offs[i + 1] = sh[t];
    if (t == 1023) partials[blockIdx.x] = sh[t];
}

__global__ void scan_phase2(int* __restrict__ partials, int nb) {
    __shared__ int sh[256];
    int t = threadIdx.x;
    sh[t] = (t < nb) ? partials[t] : 0;
    __syncthreads();
    #pragma unroll
    for (int off = 1; off < 256; off <<= 1) {
        int x = (t >= off) ? sh[t - off] : 0;
        __syncthreads();
        sh[t] += x;
        __syncthreads();
    }
    if (t < nb) partials[t] = (t == 0) ? 0 : sh[t - 1];  // exclusive
}

__global__ void scan_phase3(int* __restrict__ offs, const int* __restrict__ partials, int n) {
    int i = blockIdx.x * 1024 + threadIdx.x;
    if (i < n) offs[i + 1] += partials[blockIdx.x];
    if (i == 0) offs[0] = 0;
}

__global__ void scatter_kernel(const int* __restrict__ src, const int* __restrict__ dst,
                               int E, int* __restrict__ cursor, int* __restrict__ out_srcs) {
    int e = blockIdx.x * blockDim.x + threadIdx.x;
    if (e >= E) return;
    int d = dst[e];
    int pos = atomicAdd(&cursor[d], 1);
    out_srcs[pos] = src[e];
}

// ---------------------------------------------------------------------------
// Weight pre-split: W fp32 [K][BN] row-major -> hi/lo fp16 in [n][K] layout.
// ---------------------------------------------------------------------------
__global__ void wsplit_kernel(const float* __restrict__ W,
                              __half* __restrict__ whi, __half* __restrict__ wlo,
                              int K, int BN) {
    int t = blockIdx.x * blockDim.x + threadIdx.x;
    int total = BN * (K / 8);
    if (t >= total) return;
    int n  = t / (K / 8);
    int kq = (t % (K / 8)) * 8;
    uint4 uh, ul;
    uint32_t* ph = (uint32_t*)&uh;
    uint32_t* pl = (uint32_t*)&ul;
    #pragma unroll
    for (int i = 0; i < 4; ++i) {
        float a = W[(size_t)(kq + 2 * i) * BN + n];
        float b = W[(size_t)(kq + 2 * i + 1) * BN + n];
        __half2 h = __floats2half2_rn(a, b);
        float2 f = __half22float2(h);
        __half2 l = __floats2half2_rn(a - f.x, b - f.y);
        ph[i] = *(uint32_t*)&h;
        pl[i] = *(uint32_t*)&l;
    }
    *(uint4*)&whi[(size_t)n * K + kq] = uh;
    *(uint4*)&wlo[(size_t)n * K + kq] = ul;
}

// ---------------------------------------------------------------------------
// MMA / ldmatrix helpers
// ---------------------------------------------------------------------------
__device__ __forceinline__ void mma_f16(float* c, const uint32_t* a, const uint32_t* b) {
    asm volatile(
        "mma.sync.aligned.m16n8k16.row.col.f32.f16.f16.f32 "
        "{%0,%1,%2,%3}, {%4,%5,%6,%7}, {%8,%9}, {%0,%1,%2,%3};\n"
        : "+f"(c[0]), "+f"(c[1]), "+f"(c[2]), "+f"(c[3])
        : "r"(a[0]), "r"(a[1]), "r"(a[2]), "r"(a[3]), "r"(b[0]), "r"(b[1]));
}

__device__ __forceinline__ uint32_t smaddr(const void* p) {
    return (uint32_t)__cvta_generic_to_shared(p);
}

__device__ __forceinline__ void ldsm_x4(uint32_t* r, uint32_t addr) {
    asm volatile("ldmatrix.sync.aligned.m8n8.x4.shared.b16 {%0,%1,%2,%3}, [%4];\n"
                 : "=r"(r[0]), "=r"(r[1]), "=r"(r[2]), "=r"(r[3]) : "r"(addr));
}

__device__ __forceinline__ void ldsm_x2(uint32_t* r, uint32_t addr) {
    asm volatile("ldmatrix.sync.aligned.m8n8.x2.shared.b16 {%0,%1}, [%2];\n"
                 : "=r"(r[0]), "=r"(r[1]) : "r"(addr));
}

__device__ __forceinline__ void split8(const float* va, uint4& uh, uint4& ul) {
    uint32_t* ph = (uint32_t*)&uh;
    uint32_t* pl = (uint32_t*)&ul;
    #pragma unroll
    for (int i = 0; i < 4; ++i) {
        __half2 h = __floats2half2_rn(va[2 * i], va[2 * i + 1]);
        float2 f = __half22float2(h);
        __half2 l = __floats2half2_rn(va[2 * i] - f.x, va[2 * i + 1] - f.y);
        ph[i] = *(uint32_t*)&h;
        pl[i] = *(uint32_t*)&l;
    }
}

// ---------------------------------------------------------------------------
// GEMM: Y[N,BN] = X[N,128] @ W[128,BN] + b, fp16-split 3-pass, ldmatrix loads.
// W pre-split into hi/lo [n][K]; whole W resident in smem (K-deep).
// BM=128, BK=16, 256 threads, 8 warps (4x2), warp tile 32 x BN/2.
// ---------------------------------------------------------------------------
template <int BN>
__global__ void __launch_bounds__(256)
gemm_ldm_kernel(const float* __restrict__ X, const __half* __restrict__ Whi,
                const __half* __restrict__ Wlo, const float* __restrict__ bias,
                float* __restrict__ Y, int N) {
    constexpr int K  = 128;
    constexpr int BM = 128;
    constexpr int BK = 16;
    constexpr int AP = 24;       // A pitch (halves): conflict-free for ldmatrix
    constexpr int KP = K + 8;    // B pitch (halves) = 136: 4-word row stagger
    constexpr int WN = BN / 2;
    constexpr int FRAG_M = 2;
    constexpr int FRAG_N = WN / 8;   // 8 (BN=128) / 4 (BN=64)

    extern __shared__ __half sm[];
    __half* Ahi = sm;                     // BM*AP
    __half* Alo = Ahi + BM * AP;
    __half* Bhi = Alo + BM * AP;          // BN*KP
    __half* Blo = Bhi + BN * KP;

    int tid  = threadIdx.x;
    int wid  = tid >> 5;
    int lane = tid & 31;
    int warp_m = wid & 3;
    int warp_n = wid >> 2;
    int row0 = blockIdx.x * BM;

    // ---- load whole pre-split W into smem (coalesced uint4) ----
    for (int idx = tid * 8; idx < BN * K; idx += 256 * 8) {
        int n = idx >> 7;       // / K
        int k = idx & 127;      // % K
        *(uint4*)&Bhi[n * KP + k] = *(const uint4*)&Whi[idx];
        *(uint4*)&Blo[n * KP + k] = *(const uint4*)&Wlo[idx];
    }

    float c[FRAG_M][FRAG_N][4];
    #pragma unroll
    for (int i = 0; i < FRAG_M; ++i)
        #pragma unroll
        for (int j = 0; j < FRAG_N; ++j)
            #pragma unroll
            for (int k = 0; k < 4; ++k) c[i][j][k] = 0.f;

    // A staging map: thread -> (row xr, k-octet xkb)
    int xr  = tid >> 1;
    int xkb = (tid & 1) * 8;
    bool xvalid = (row0 + xr) < N;
    const float* xb = X + (size_t)(row0 + xr) * K + xkb;

    // prefetch first tile
    float4 v0 = make_float4(0.f, 0.f, 0.f, 0.f), v1 = v0;
    if (xvalid) { v0 = *(const float4*)(xb); v1 = *(const float4*)(xb + 4); }

    // ldmatrix A addresses (fixed across tiles)
    uint32_t a_ad_hi[FRAG_M], a_ad_lo[FRAG_M];
    #pragma unroll
    for (int fm = 0; fm < FRAG_M; ++fm) {
        int r = warp_m * 32 + fm * 16 + (lane & 15);
        int kofs = (lane >> 4) * 8;
        a_ad_hi[fm] = smaddr(&Ahi[r * AP + kofs]);
        a_ad_lo[fm] = smaddr(&Alo[r * AP + kofs]);
    }
    int bn_row = warp_n * WN + (lane & 7);
    int bk_off = ((lane >> 3) & 1) * 8;

    for (int kt = 0; kt < K; kt += BK) {
        // ---- store staged A tile (vectorized) ----
        {
            float va[8] = {v0.x, v0.y, v0.z, v0.w, v1.x, v1.y, v1.z, v1.w};
            uint4 uh, ul;
            split8(va, uh, ul);
            *(uint4*)&Ahi[xr * AP + xkb] = uh;
            *(uint4*)&Alo[xr * AP + xkb] = ul;
        }
        __syncthreads();

        // ---- fragments via ldmatrix ----
        uint32_t ah[FRAG_M][4], al[FRAG_M][4];
        #pragma unroll
        for (int fm = 0; fm < FRAG_M; ++fm) {
            ldsm_x4(ah[fm], a_ad_hi[fm]);
            ldsm_x4(al[fm], a_ad_lo[fm]);
        }
        uint32_t bh[FRAG_N][2], bl[FRAG_N][2];
        #pragma unroll
        for (int fn = 0; fn < FRAG_N; ++fn) {
            int nr = (bn_row + fn * 8) * KP + kt + bk_off;
            ldsm_x2(bh[fn], smaddr(&Bhi[nr]));
            ldsm_x2(bl[fn], smaddr(&Blo[nr]));
        }

        // ---- prefetch next A tile while MMAs run ----
        if (kt + BK < K && xvalid) {
            v0 = *(const float4*)(xb + kt + BK);
            v1 = *(const float4*)(xb + kt + BK + 4);
        }

        #pragma unroll
        for (int fm = 0; fm < FRAG_M; ++fm)
            #pragma unroll
            for (int fn = 0; fn < FRAG_N; ++fn) {
                mma_f16(c[fm][fn], ah[fm], bh[fn]);
                mma_f16(c[fm][fn], ah[fm], bl[fn]);
                mma_f16(c[fm][fn], al[fm], bh[fn]);
            }
        __syncthreads();
    }

    // ---- epilogue: add bias, store ----
    int er  = row0 + warp_m * 32 + (lane >> 2);
    int ec0 = warp_n * WN + (lane & 3) * 2;
    #pragma unroll
    for (int fn = 0; fn < FRAG_N; ++fn) {
        int col = ec0 + fn * 8;
        float b0 = bias[col], b1 = bias[col + 1];
        #pragma unroll
        for (int fm = 0; fm < FRAG_M; ++fm) {
            int r = er + fm * 16;
            if (r < N) {
                float2 o = make_float2(c[fm][fn][0] + b0, c[fm][fn][1] + b1);
                *(float2*)&Y[(size_t)r * BN + col] = o;
            }
            if (r + 8 < N) {
                float2 o = make_float2(c[fm][fn][2] + b0, c[fm][fn][3] + b1);
                *(float2*)&Y[(size_t)(r + 8) * BN + col] = o;
            }
        }
    }
}

// ---------------------------------------------------------------------------
// Fused per-node attention logits: one read of H, both src and dst dots.
// ---------------------------------------------------------------------------
template <int F>
__global__ void alpha2_kernel(const float* __restrict__ Hf,
                              const float* __restrict__ avs, const float* __restrict__ avd,
                              float* __restrict__ outs, float* __restrict__ outd, int N) {
    int i = blockIdx.x * blockDim.x + threadIdx.x;
    if (i >= N * H4) return;
    int n = i >> 2, h = i & 3;
    constexpr int D = F / 4;
    const float4* row = (const float4*)(Hf + (size_t)n * F + h * D);
    const float4* as = (const float4*)(avs + h * D);
    const float4* ad = (const float4*)(avd + h * D);
    float ss = 0.f, sd = 0.f;
    #pragma unroll
    for (int d = 0; d < D / 4; ++d) {
        float4 hv = row[d], a = as[d], b = ad[d];
        ss += hv.x * a.x + hv.y * a.y + hv.z * a.z + hv.w * a.w;
        sd += hv.x * b.x + hv.y * b.y + hv.z * b.z + hv.w * b.w;
    }
    outs[i] = ss;
    outd[i] = sd;
}

// ---------------------------------------------------------------------------
// Edge-softmax aggregation, warp per dst node, online softmax, atomic-free.
// ---------------------------------------------------------------------------
template <int F>
__global__ void __launch_bounds__(256)
aggregate_kernel(const float* __restrict__ Hsrc, const float* __restrict__ asrc,
                 const float* __restrict__ adst, const int* __restrict__ offs,
                 const int* __restrict__ srcs, float* __restrict__ Out, int Ndst) {
    constexpr int VEC = F / 32;
    int wid = (blockIdx.x * blockDim.x + threadIdx.x) >> 5;
    int lane = threadIdx.x & 31;
    if (wid >= Ndst) return;
    int beg = offs[wid], end = offs[wid + 1];
    int head = lane >> 3;
    float ad = adst[wid * H4 + head];
    float m = -3.4e38f, l = 0.f;
    float acc[VEC];
    #pragma unroll
    for (int v = 0; v < VEC; ++v) acc[v] = 0.f;

    int s_next = (beg < end) ? srcs[beg] : 0;
    for (int j = beg; j < end; ++j) {
        int s = s_next;
        if (j + 1 < end) s_next = srcs[j + 1];
        float a = asrc[s * H4 + head] + ad;
        a = (a >= 0.f) ? a : 0.2f * a;
        float mn = fmaxf(m, a);
        float sc = __expf(m - mn);
        float e  = __expf(a - mn);
        l = l * sc + e;
        const float* hp = Hsrc + (size_t)s * F + lane * VEC;
        if (VEC == 4) {
            float4 hv = *(const float4*)hp;
            acc[0] = acc[0] * sc + e * hv.x;
            acc[1] = acc[1] * sc + e * hv.y;
            acc[2] = acc[2] * sc + e * hv.z;
            acc[3] = acc[3] * sc + e * hv.w;
        } else {
            float2 hv = *(const float2*)hp;
            acc[0] = acc[0] * sc + e * hv.x;
            acc[1] = acc[1] * sc + e * hv.y;
        }
        m = mn;
    }
    float inv = 1.f / (l + 1e-16f);
    float* op = Out + (size_t)wid * F + lane * VEC;
    #pragma unroll
    for (int v = 0; v < VEC; ++v) op[v] = fmaxf(acc[v] * inv, 0.f);
}

// ---------------------------------------------------------------------------
// Final link prediction
// ---------------------------------------------------------------------------
__global__ void edge_dot_kernel(const float* __restrict__ zp, const float* __restrict__ za,
                                const int* __restrict__ eli, float* __restrict__ out, int L) {
    int t = blockIdx.x * blockDim.x + threadIdx.x;
    int edge = t >> 4;
    int sub = t & 15;
    if (edge >= L) return;
    int p = eli[edge];
    int a = eli[L + edge];
    float4 u = *(const float4*)(zp + (size_t)p * 64 + sub * 4);
    float4 v = *(const float4*)(za + (size_t)a * 64 + sub * 4);
    float s = u.x * v.x + u.y * v.y + u.z * v.z + u.w * v.w;
    s += __shfl_xor_sync(0xffffffffu, s, 8);
    s += __shfl_xor_sync(0xffffffffu, s, 4);
    s += __shfl_xor_sync(0xffffffffu, s, 2);
    s += __shfl_xor_sync(0xffffffffu, s, 1);
    if (sub == 0) out[edge] = s;
}

// ---------------------------------------------------------------------------
// Host orchestration
// ---------------------------------------------------------------------------
extern "C" void kernel_launch(void* const* d_in, const int* in_sizes, int n_in,
                              void* d_out, int out_size) {
    const float* x_paper  = (const float*)d_in[0];
    const float* x_author = (const float*)d_in[1];
    const int*   ei_pa    = (const int*)d_in[2];
    const int*   ei_ap    = (const int*)d_in[3];
    const int*   eli      = (const int*)d_in[4];
    const float* p1W = (const float*)d_in[5];
    const float* p1b = (const float*)d_in[6];
    const float* a1W = (const float*)d_in[7];
    const float* a1b = (const float*)d_in[8];
    const float* s1pa = (const float*)d_in[9];
    const float* d1pa = (const float*)d_in[10];
    const float* s1ap = (const float*)d_in[11];
    const float* d1ap = (const float*)d_in[12];
    // d_in[13..15]: k1W,k1b,q1 dead (_group over one metapath == identity)
    const float* p2W = (const float*)d_in[16];
    const float* p2b = (const float*)d_in[17];
    const float* a2W = (const float*)d_in[18];
    const float* a2b = (const float*)d_in[19];
    const float* s2pa = (const float*)d_in[20];
    const float* d2pa = (const float*)d_in[21];
    const float* s2ap = (const float*)d_in[22];
    const float* d2ap = (const float*)d_in[23];
    // d_in[24..26]: k2W,k2b,q2 dead

    int NP = in_sizes[0] / 128;
    int NA = in_sizes[1] / 128;
    int E  = in_sizes[2] / 2;
    int L  = in_sizes[4] / 2;

    float *hp, *ha, *zp, *za, *asrc_pa, *adst_pa, *asrc_ap, *adst_ap;
    int *offs_pa, *offs_ap, *srcs_pa, *srcs_ap, *cnt, *cnt2, *partials, *partials2;
    __half *wh, *wl;
    cudaGetSymbolAddress((void**)&hp, g_hp);
    cudaGetSymbolAddress((void**)&ha, g_ha);
    cudaGetSymbolAddress((void**)&zp, g_zp);
    cudaGetSymbolAddress((void**)&za, g_za);
    cudaGetSymbolAddress((void**)&asrc_pa, g_asrc_pa);
    cudaGetSymbolAddress((void**)&adst_pa, g_adst_pa);
    cudaGetSymbolAddress((void**)&asrc_ap, g_asrc_ap);
    cudaGetSymbolAddress((void**)&adst_ap, g_adst_ap);
    cudaGetSymbolAddress((void**)&offs_pa, g_offs_pa);
    cudaGetSymbolAddress((void**)&offs_ap, g_offs_ap);
    cudaGetSymbolAddress((void**)&srcs_pa, g_srcs_pa);
    cudaGetSymbolAddress((void**)&srcs_ap, g_srcs_ap);
    cudaGetSymbolAddress((void**)&cnt, g_cnt);
    cudaGetSymbolAddress((void**)&cnt2, g_cnt2);
    cudaGetSymbolAddress((void**)&partials, g_partials);
    cudaGetSymbolAddress((void**)&partials2, g_partials2);
    cudaGetSymbolAddress((void**)&wh, g_wh);
    cudaGetSymbolAddress((void**)&wl, g_wl);
    __half* wh1p = wh;               __half* wl1p = wl;
    __half* wh1a = wh + 16384;       __half* wl1a = wl + 16384;
    __half* wh2p = wh + 2 * 16384;   __half* wl2p = wl + 2 * 16384;
    __half* wh2a = wh + 3 * 16384;   __half* wl2a = wl + 3 * 16384;

    // opt-in smem (idempotent)
    constexpr int SM128 = (2 * 128 * 24 + 2 * 128 * 136) * 2;   // 81920
    constexpr int SM64  = (2 * 128 * 24 + 2 * 64 * 136) * 2;    // 47104
    cudaFuncSetAttribute(gemm_ldm_kernel<128>, cudaFuncAttributeMaxDynamicSharedMemorySize, SM128);
    cudaFuncSetAttribute(gemm_ldm_kernel<64>,  cudaFuncAttributeMaxDynamicSharedMemorySize, SM64);

    // side stream + events (host-side objects; created once)
    static cudaStream_t s1 = nullptr;
    static cudaEvent_t evA = nullptr, evB = nullptr;
    if (!s1) {
        cudaStreamCreateWithFlags(&s1, cudaStreamNonBlocking);
        cudaEventCreateWithFlags(&evA, cudaEventDisableTiming);
        cudaEventCreateWithFlags(&evB, cudaEventDisableTiming);
    }

    int gb_p = (NP + 127) / 128;
    int gb_a = (NA + 127) / 128;
    int at_p = (NP * H4 + 255) / 256;
    int at_a = (NA * H4 + 255) / 256;
    int ag_a = (NA * 32 + 255) / 256;
    int ag_p = (NP * 32 + 255) / 256;
    int nb   = (NMAX + 1023) / 1024;
    int ws128 = (128 * 16 + 255) / 256;   // wsplit grid for BN=128
    int ws64  = (64 * 16 + 255) / 256;

    // ---- main stream: kernels 1-3, then the captured GEMM (#4) ----
    wsplit_kernel<<<ws128, 256>>>(p1W, wh1p, wl1p, 128, 128);                 // k1
    hist_kernel<<<(E + 255) / 256, 256>>>(ei_pa + E, E, cnt);                 // k2 (cnt is zero-init static)
    scan_phase1<<<nb, 1024>>>(cnt, NA, offs_pa, partials);                    // k3
    gemm_ldm_kernel<128><<<gb_p, 256, SM128>>>(x_paper, wh1p, wl1p, p1b, hp, NP);  // k4 <- ncu
    cudaEventRecord(evA, 0);

    // ---- side stream: CSR-ap + layer-2 weight splits (hidden behind gemms) ----
    cudaStreamWaitEvent(s1, evA, 0);
    cudaMemsetAsync(cnt2, 0, (size_t)NP * sizeof(int), s1);
    hist_kernel<<<(E + 255) / 256, 256, 0, s1>>>(ei_ap + E, E, cnt2);
    scan_phase1<<<nb, 1024, 0, s1>>>(cnt2, NP, offs_ap, partials2);
    scan_phase2<<<1, 256, 0, s1>>>(partials2, nb);
    scan_phase3<<<nb, 1024, 0, s1>>>(offs_ap, partials2, NP);
    cudaMemcpyAsync(cnt2, offs_ap, (size_t)NP * sizeof(int), cudaMemcpyDeviceToDevice, s1);
    scatter_kernel<<<(E + 255) / 256, 256, 0, s1>>>(ei_ap, ei_ap + E, E, cnt2, srcs_ap);
    wsplit_kernel<<<ws64, 256, 0, s1>>>(p2W, wh2p, wl2p, 128, 64);
    wsplit_kernel<<<ws64, 256, 0, s1>>>(a2W, wh2a, wl2a, 128, 64);
    cudaEventRecord(evB, s1);

    // ---- main stream continues: finish CSR-pa, 2nd gemm, attention ----
    scan_phase2<<<1, 256>>>(partials, nb);
    scan_phase3<<<nb, 1024>>>(offs_pa, partials, NA);
    cudaMemcpyAsync(cnt, offs_pa, (size_t)NA * sizeof(int), cudaMemcpyDeviceToDevice);
    scatter_kernel<<<(E + 255) / 256, 256>>>(ei_pa, ei_pa + E, E, cnt, srcs_pa);
    cudaMemsetAsync(cnt, 0, (size_t)NA * sizeof(int));   // re-zero for next call
    wsplit_kernel<<<ws128, 256>>>(a1W, wh1a, wl1a, 128, 128);
    gemm_ldm_kernel<128><<<gb_a, 256, SM128>>>(x_author, wh1a, wl1a, a1b, ha, NA);

    alpha2_kernel<128><<<at_p, 256>>>(hp, s1pa, d1ap, asrc_pa, adst_ap, NP);
    alpha2_kernel<128><<<at_a, 256>>>(ha, s1ap, d1pa, asrc_ap, adst_pa, NA);
    aggregate_kernel<128><<<ag_a, 256>>>(hp, asrc_pa, adst_pa, offs_pa, srcs_pa, za, NA);
    cudaStreamWaitEvent(0, evB, 0);     // need CSR-ap (+ layer-2 W splits) done
    aggregate_kernel<128><<<ag_p, 256>>>(ha, asrc_ap, adst_ap, offs_ap, srcs_ap, zp, NP);

    // ---- Layer 2 (K=128 -> F=64) ----
    gemm_ldm_kernel<64><<<gb_p, 256, SM64>>>(zp, wh2p, wl2p, p2b, hp, NP);
    gemm_ldm_kernel<64><<<gb_a, 256, SM64>>>(za, wh2a, wl2a, a2b, ha, NA);
    alpha2_kernel<64><<<at_p, 256>>>(hp, s2pa, d2ap, asrc_pa, adst_ap, NP);
    alpha2_kernel<64><<<at_a, 256>>>(ha, s2ap, d2pa, asrc_ap, adst_pa, NA);
    aggregate_kernel<64><<<ag_a, 256>>>(hp, asrc_pa, adst_pa, offs_pa, srcs_pa, za, NA);
    aggregate_kernel<64><<<ag_p, 256>>>(ha, asrc_ap, adst_ap, offs_ap, srcs_ap, zp, NP);

    // ---- Link prediction ----
    edge_dot_kernel<<<(L * 16 + 255) / 256, 256>>>(zp, za, eli, (float*)d_out, L);
}